// round 8
// baseline (speedup 1.0000x reference)
#include <cuda_runtime.h>
#include <cuda_bf16.h>
#include <cstdint>

// Problem constants
#define NSRC 100000
#define NDST 100000
#define NE   500000
#define DIM  128
#define NLAY 2
#define TILES 782            // ceil(100000/128)
#define PCTAS 74             // persistent CTAs per direction
#define SCAN_BLK 98          // ceil(100000/1024)

// ---------------------------------------------------------------------------
// Scratch (device globals: allocation-free, graph-capture safe)
// ---------------------------------------------------------------------------
__device__ __nv_bfloat16 g_xs_hi[NSRC * DIM], g_xs_lo[NSRC * DIM];
__device__ __nv_bfloat16 g_xd_hi[NDST * DIM], g_xd_lo[NDST * DIM];
__device__ __nv_bfloat16 g_hs_hi[NSRC * DIM], g_hs_lo[NSRC * DIM];
__device__ __nv_bfloat16 g_hd_hi[NDST * DIM], g_hd_lo[NDST * DIM];
__device__ __nv_bfloat16 g_aggs_hi[NSRC * DIM], g_aggs_lo[NSRC * DIM];
__device__ __nv_bfloat16 g_aggd_hi[NDST * DIM], g_aggd_lo[NDST * DIM];
// CSR structures
__device__ int g_off_d[NDST + 1];
__device__ int g_off_s[NSRC + 1];
__device__ int g_cur_d[NDST];
__device__ int g_cur_s[NSRC];
__device__ int g_adj_d[NE];
__device__ int g_adj_s[NE];
__device__ int g_part[2][128];
// bf16 hi/lo weight images: [layer][dir][hi/lo][n=128][k=256]
__device__ __nv_bfloat16 g_Bbf[NLAY][2][2][DIM * 256];

// ---------------------------------------------------------------------------
__device__ __forceinline__ void split2(float x, float y, uint32_t& h, uint32_t& l) {
    asm("cvt.rn.bf16x2.f32 %0, %1, %2;" : "=r"(h) : "f"(y), "f"(x));
    float hx = __uint_as_float(h << 16), hy = __uint_as_float(h & 0xffff0000u);
    asm("cvt.rn.bf16x2.f32 %0, %1, %2;" : "=r"(l) : "f"(y - hy), "f"(x - hx));
}

// ---------------------------------------------------------------------------
// Fused prologue: prep_X (blocks [0,12500)), zero_cnt ([12500,12891)),
// prep_B ([12891,13403)). All independent.
// ---------------------------------------------------------------------------
#define PREPX_BLKS 12500
#define ZERO_BLKS  391
#define PREPB_BLKS 512
__global__ void __launch_bounds__(256) k_prep(
    const float* __restrict__ xs, const float* __restrict__ xd,
    const float* __restrict__ Wss, const float* __restrict__ Wsn,
    const float* __restrict__ Wrs, const float* __restrict__ Wrn)
{
    int b = blockIdx.x;
    if (b < PREPX_BLKS) {
        int i = b * 256 + threadIdx.x;           // float4 index
        const int n4 = NSRC * DIM / 4;
        if (i >= n4) return;
        float4 v = __ldg((const float4*)xs + i);
        uint32_t h0, h1, l0, l1;
        split2(v.x, v.y, h0, l0); split2(v.z, v.w, h1, l1);
        *(uint2*)&g_xs_hi[i * 4] = make_uint2(h0, h1);
        *(uint2*)&g_xs_lo[i * 4] = make_uint2(l0, l1);
        v = __ldg((const float4*)xd + i);
        split2(v.x, v.y, h0, l0); split2(v.z, v.w, h1, l1);
        *(uint2*)&g_xd_hi[i * 4] = make_uint2(h0, h1);
        *(uint2*)&g_xd_lo[i * 4] = make_uint2(l0, l1);
    } else if (b < PREPX_BLKS + ZERO_BLKS) {
        int i = (b - PREPX_BLKS) * 256 + threadIdx.x;
        if (i < NDST) { g_cur_d[i] = 0; g_cur_s[i] = 0; }
    } else {
        int bb = b - PREPX_BLKS - ZERO_BLKS;     // 0..511; 128 blocks per image
        int img = bb >> 7;                       // l*2+d
        int l = img >> 1, d = img & 1;
        const float* Wself  = (d == 0 ? Wss : Wrs) + l * DIM * DIM;
        const float* Wneigh = (d == 0 ? Wsn : Wrn) + l * DIM * DIM;
        int i = (bb & 127) * 256 + threadIdx.x;  // 0..32767
        int n = i >> 8;
        int k = i & 255;
        float v = (k < DIM) ? __ldg(&Wself[n * DIM + k]) : __ldg(&Wneigh[n * DIM + (k - DIM)]);
        __nv_bfloat16 hi = __float2bfloat16(v);
        __nv_bfloat16 lo = __float2bfloat16(v - __bfloat162float(hi));
        g_Bbf[l][d][0][i] = hi;
        g_Bbf[l][d][1][i] = lo;
    }
}

// ---------------------------------------------------------------------------
// CSR build
// ---------------------------------------------------------------------------
__global__ void k_count(const int* __restrict__ es, const int* __restrict__ ed) {
    int i = blockIdx.x * blockDim.x + threadIdx.x;   // pair index
    if (i * 2 + 1 < NE) {
        int2 e2 = __ldg((const int2*)ed + i);
        int2 s2 = __ldg((const int2*)es + i);
        atomicAdd(&g_cur_d[e2.x], 1);
        atomicAdd(&g_cur_d[e2.y], 1);
        atomicAdd(&g_cur_s[s2.x], 1);
        atomicAdd(&g_cur_s[s2.y], 1);
    } else if (i * 2 < NE) {
        atomicAdd(&g_cur_d[__ldg(&ed[i * 2])], 1);
        atomicAdd(&g_cur_s[__ldg(&es[i * 2])], 1);
    }
}
__global__ void k_blocksum() {
    const int a = blockIdx.y;
    const int* cnt = a ? g_cur_s : g_cur_d;
    __shared__ int sm[256];
    int base = blockIdx.x * 1024 + threadIdx.x * 4;
    int s = 0;
#pragma unroll
    for (int q = 0; q < 4; q++) { int i = base + q; if (i < NDST) s += cnt[i]; }
    sm[threadIdx.x] = s; __syncthreads();
    for (int st = 128; st > 0; st >>= 1) {
        if (threadIdx.x < st) sm[threadIdx.x] += sm[threadIdx.x + st];
        __syncthreads();
    }
    if (threadIdx.x == 0) g_part[a][blockIdx.x] = sm[0];
}
__global__ void k_write_off() {
    const int a = blockIdx.y;
    int* cnt = a ? g_cur_s : g_cur_d;
    int* off = a ? g_off_s : g_off_d;
    __shared__ int sm[256];
    __shared__ int s_pre;
    const int t = threadIdx.x;
    if (t == 0) {
        int p = 0;
        for (int b2 = 0; b2 < blockIdx.x; b2++) p += __ldg(&g_part[a][b2]);
        s_pre = p;
    }
    const int i0 = blockIdx.x * 1024 + t * 4;
    int c[4]; int ts = 0;
#pragma unroll
    for (int q = 0; q < 4; q++) { int i = i0 + q; c[q] = (i < NDST) ? cnt[i] : 0; ts += c[q]; }
    sm[t] = ts; __syncthreads();
    for (int st = 1; st < 256; st <<= 1) {
        int u = (t >= st) ? sm[t - st] : 0;
        __syncthreads();
        sm[t] += u;
        __syncthreads();
    }
    int excl = sm[t] - ts + s_pre;
#pragma unroll
    for (int q = 0; q < 4; q++) {
        int i = i0 + q;
        if (i < NDST) {
            off[i] = excl;
            cnt[i] = excl;
            if (i == NDST - 1) off[NDST] = excl + c[q];
            excl += c[q];
        }
    }
}
__global__ void k_place(const int* __restrict__ es, const int* __restrict__ ed) {
    int i = blockIdx.x * blockDim.x + threadIdx.x;
    if (i >= NE) return;
    int s = __ldg(&es[i]), d = __ldg(&ed[i]);
    int pd = atomicAdd(&g_cur_d[d], 1);
    g_adj_d[pd] = s;
    int ps = atomicAdd(&g_cur_s[s], 1);
    g_adj_s[ps] = d;
}

// ---------------------------------------------------------------------------
// CSR gather: one warp per (node, dir), mean folded in, bf16 hi/lo plane output
// ---------------------------------------------------------------------------
__device__ __forceinline__ void acc_bf4(float4& acc, uint2 H, uint2 L) {
    float2 fh0 = __bfloat1622float2(*(__nv_bfloat162*)&H.x);
    float2 fh1 = __bfloat1622float2(*(__nv_bfloat162*)&H.y);
    float2 fl0 = __bfloat1622float2(*(__nv_bfloat162*)&L.x);
    float2 fl1 = __bfloat1622float2(*(__nv_bfloat162*)&L.y);
    acc.x += fh0.x + fl0.x; acc.y += fh0.y + fl0.y;
    acc.z += fh1.x + fl1.x; acc.w += fh1.y + fl1.y;
}

__global__ void __launch_bounds__(256) k_gather(
    int layer, const float* __restrict__ xs, const float* __restrict__ xd)
{
    int w = (blockIdx.x * blockDim.x + threadIdx.x) >> 5;
    if (w >= 2 * NDST) return;
    const int lane = threadIdx.x & 31;
    int node, dir;
    if (w < NDST) { node = w; dir = 0; } else { node = w - NDST; dir = 1; }

    const int *off, *adj; const float* featf;
    const __nv_bfloat16 *fh, *fl;
    __nv_bfloat16 *oh, *ol;
    if (dir == 0) {
        off = g_off_d; adj = g_adj_d;
        featf = xs; fh = g_hs_hi; fl = g_hs_lo;
        oh = g_aggd_hi; ol = g_aggd_lo;
    } else {
        off = g_off_s; adj = g_adj_s;
        featf = xd; fh = g_hd_hi; fl = g_hd_lo;
        oh = g_aggs_hi; ol = g_aggs_lo;
    }

    const int b = off[node], e = off[node + 1];
    const int c = lane * 4;
    float4 acc = make_float4(0.f, 0.f, 0.f, 0.f);
    if (layer == 0) {
        int j = b;
        for (; j + 3 < e; j += 4) {                    // 4 rows in flight
            int r0 = __ldg(&adj[j]);
            int r1 = __ldg(&adj[j + 1]);
            int r2 = __ldg(&adj[j + 2]);
            int r3 = __ldg(&adj[j + 3]);
            float4 v0 = __ldg((const float4*)&featf[(size_t)r0 * DIM + c]);
            float4 v1 = __ldg((const float4*)&featf[(size_t)r1 * DIM + c]);
            float4 v2 = __ldg((const float4*)&featf[(size_t)r2 * DIM + c]);
            float4 v3 = __ldg((const float4*)&featf[(size_t)r3 * DIM + c]);
            acc.x += (v0.x + v1.x) + (v2.x + v3.x);
            acc.y += (v0.y + v1.y) + (v2.y + v3.y);
            acc.z += (v0.z + v1.z) + (v2.z + v3.z);
            acc.w += (v0.w + v1.w) + (v2.w + v3.w);
        }
        for (; j < e; j++) {
            int r0 = __ldg(&adj[j]);
            float4 v0 = __ldg((const float4*)&featf[(size_t)r0 * DIM + c]);
            acc.x += v0.x; acc.y += v0.y; acc.z += v0.z; acc.w += v0.w;
        }
    } else {
        int j = b;
        for (; j + 1 < e; j += 2) {                    // 4 loads in flight
            int r0 = __ldg(&adj[j]);
            int r1 = __ldg(&adj[j + 1]);
            uint2 H0 = __ldg((const uint2*)&fh[(size_t)r0 * DIM + c]);
            uint2 L0 = __ldg((const uint2*)&fl[(size_t)r0 * DIM + c]);
            uint2 H1 = __ldg((const uint2*)&fh[(size_t)r1 * DIM + c]);
            uint2 L1 = __ldg((const uint2*)&fl[(size_t)r1 * DIM + c]);
            acc_bf4(acc, H0, L0);
            acc_bf4(acc, H1, L1);
        }
        if (j < e) {
            int r0 = __ldg(&adj[j]);
            uint2 H0 = __ldg((const uint2*)&fh[(size_t)r0 * DIM + c]);
            uint2 L0 = __ldg((const uint2*)&fl[(size_t)r0 * DIM + c]);
            acc_bf4(acc, H0, L0);
        }
    }
    const float s = 1.0f / fmaxf((float)(e - b), 1.0f);
    acc.x *= s; acc.y *= s; acc.z *= s; acc.w *= s;

    uint32_t h0, h1, l0, l1;
    split2(acc.x, acc.y, h0, l0);
    split2(acc.z, acc.w, h1, l1);
    *(uint2*)&oh[(size_t)node * DIM + c] = make_uint2(h0, h1);
    *(uint2*)&ol[(size_t)node * DIM + c] = make_uint2(l0, l1);
}

// ---------------------------------------------------------------------------
// Persistent pipelined mma.sync GEMM (3-term hi/lo split, unique fragments,
// single __syncthreads per chunk)
// ---------------------------------------------------------------------------
#define SPAD 72
#define PLANE_B 18432
#define AREG_B 73728
#define BREG_B 147456
#define SM_BIAS_B (AREG_B + BREG_B)
#define SM_TOTAL (SM_BIAS_B + 512)

__device__ __forceinline__ uint32_t smem_u32(const void* p) {
    uint32_t a;
    asm("{ .reg .u64 t; cvta.to.shared.u64 t, %1; cvt.u32.u64 %0, t; }" : "=r"(a) : "l"(p));
    return a;
}
#define CP_ASYNC16(dst, src) \
    asm volatile("cp.async.cg.shared.global [%0], [%1], 16;" :: "r"(dst), "l"(src))
#define CP_COMMIT() asm volatile("cp.async.commit_group;")
#define CP_WAIT0()  asm volatile("cp.async.wait_group 0;")

#define LDSM_X4(r, addr) \
    asm volatile("ldmatrix.sync.aligned.m8n8.x4.shared.b16 {%0,%1,%2,%3}, [%4];" \
        : "=r"((r)[0]), "=r"((r)[1]), "=r"((r)[2]), "=r"((r)[3]) : "r"(addr))

#define MMA_BF16(c, a, b0, b1) \
    asm volatile("mma.sync.aligned.m16n8k16.row.col.f32.bf16.bf16.f32 " \
        "{%0,%1,%2,%3}, {%4,%5,%6,%7}, {%8,%9}, {%0,%1,%2,%3};" \
        : "+f"((c)[0]), "+f"((c)[1]), "+f"((c)[2]), "+f"((c)[3]) \
        : "r"((a)[0]), "r"((a)[1]), "r"((a)[2]), "r"((a)[3]), "r"(b0), "r"(b1))

__global__ void __launch_bounds__(256, 1) k_gemm(
    int layer, const float* __restrict__ bsh, const float* __restrict__ brv,
    float* __restrict__ dout)
{
    extern __shared__ unsigned char smraw[];
    __nv_bfloat16* sm = (__nv_bfloat16*)smraw;
    float* sbias = (float*)(smraw + SM_BIAS_B);

    const int tid  = threadIdx.x;
    const int wid  = tid >> 5, lane = tid & 31;
    const int dir  = blockIdx.y;
    const int wm   = wid & 1;
    const int wn   = wid >> 1;
    const uint32_t smb = smem_u32(sm);

    const float* bias;
    const __nv_bfloat16 *Sh, *Sl, *Gh, *Gl;
    __nv_bfloat16 *Oh, *Ol;
    float* outf;
    if (dir == 0) {
        Sh = layer ? g_hd_hi : g_xd_hi;  Sl = layer ? g_hd_lo : g_xd_lo;
        Gh = g_aggd_hi; Gl = g_aggd_lo;
        Oh = g_hd_hi; Ol = g_hd_lo;
        bias = bsh + layer * DIM;
        outf = dout + (size_t)NSRC * DIM;
    } else {
        Sh = layer ? g_hs_hi : g_xs_hi;  Sl = layer ? g_hs_lo : g_xs_lo;
        Gh = g_aggs_hi; Gl = g_aggs_lo;
        Oh = g_hs_hi; Ol = g_hs_lo;
        bias = brv + layer * DIM;
        outf = dout;
    }
    const __nv_bfloat16* Bhg = g_Bbf[layer][dir][0];
    const __nv_bfloat16* Blg = g_Bbf[layer][dir][1];

    // ---- B: all 4 chunks hi/lo via cp.async ----
#pragma unroll 4
    for (int j = 0; j < 32; j++) {
        int i = j * 256 + tid;
        int pc = i >> 10;
        int cch = pc >> 1, pp = pc & 1;
        int rem = i & 1023;
        int rowi = rem >> 3, piece = rem & 7;
        const __nv_bfloat16* src = (pp ? Blg : Bhg) + rowi * 256 + cch * 64 + piece * 8;
        uint32_t dst = smb + AREG_B + pc * PLANE_B + rowi * 144 + piece * 16;
        CP_ASYNC16(dst, src);
    }
    if (tid < DIM) sbias[tid] = bias[tid];

    const int a_row_off = (wm * 64 + (lane & 15)) * SPAD + (lane >> 4) * 8;
    const int b_row_off = (wn * 32 + (lane & 7) + (lane >> 4) * 8) * SPAD + ((lane >> 3) & 1) * 8;

    auto issue_A = [&](int tile, int kc, int st) {
        const __nv_bfloat16* ph = (kc < 2) ? Sh : Gh;
        const __nv_bfloat16* pl = (kc < 2) ? Sl : Gl;
        const int col0 = (kc & 1) * 64;
#pragma unroll
        for (int j = 0; j < 8; j++) {
            int i = j * 256 + tid;
            int pp = i >> 10;
            int rem = i & 1023;
            int rowi = rem >> 3, piece = rem & 7;
            int r = tile * 128 + rowi; if (r > NDST - 1) r = NDST - 1;
            const __nv_bfloat16* src = (pp ? pl : ph) + (size_t)r * DIM + col0 + piece * 8;
            uint32_t dst = smb + (st * 2 + pp) * PLANE_B + rowi * 144 + piece * 16;
            CP_ASYNC16(dst, src);
        }
    };

    // prologue: chunk 0 of first tile (grouped together with B)
    int st = 0;
    issue_A(blockIdx.x, 0, 0);
    CP_COMMIT();

    for (int tile = blockIdx.x; tile < TILES; tile += PCTAS) {
        float acc[4][4][4];
#pragma unroll
        for (int i = 0; i < 4; i++)
#pragma unroll
            for (int j = 0; j < 4; j++)
#pragma unroll
                for (int q = 0; q < 4; q++) acc[i][j][q] = 0.f;

#pragma unroll 1
        for (int kc = 0; kc < 4; kc++) {
            CP_WAIT0();              // current chunk's data arrived (committed last iter)
            __syncthreads();         // visible to all; also frees st^1 for overwrite

            int ntile = (kc < 3) ? tile : tile + PCTAS;
            int nkc   = (kc < 3) ? kc + 1 : 0;
            if (ntile < TILES) { issue_A(ntile, nkc, st ^ 1); }
            CP_COMMIT();             // copies fly while we compute

            const uint32_t aHi = smb + (st * 2) * PLANE_B + 2 * a_row_off;
            const uint32_t aLo = aHi + PLANE_B;
            const uint32_t bHi = smb + AREG_B + (kc * 2) * PLANE_B + 2 * b_row_off;
            const uint32_t bLo = bHi + PLANE_B;
#pragma unroll
            for (int k16 = 0; k16 < 4; k16++) {
                uint32_t ah[4][4], al[4][4], bh[2][4], bl[2][4];
#pragma unroll
                for (int mt = 0; mt < 4; mt++) {
                    LDSM_X4(ah[mt], aHi + 2 * (mt * 16 * SPAD + k16 * 16));
                    LDSM_X4(al[mt], aLo + 2 * (mt * 16 * SPAD + k16 * 16));
                }
#pragma unroll
                for (int p = 0; p < 2; p++) {
                    LDSM_X4(bh[p], bHi + 2 * (p * 16 * SPAD + k16 * 16));
                    LDSM_X4(bl[p], bLo + 2 * (p * 16 * SPAD + k16 * 16));
                }
#pragma unroll
                for (int mt = 0; mt < 4; mt++)
#pragma unroll
                    for (int nt = 0; nt < 4; nt++) {
                        uint32_t* BH = &bh[nt >> 1][(nt & 1) * 2];
                        uint32_t* BL = &bl[nt >> 1][(nt & 1) * 2];
                        MMA_BF16(acc[mt][nt], ah[mt], BH[0], BH[1]);
                        MMA_BF16(acc[mt][nt], al[mt], BH[0], BH[1]);
                        MMA_BF16(acc[mt][nt], ah[mt], BL[0], BL[1]);
                    }
            }
            st ^= 1;
        }

        // ---- epilogue (no smem dependence on A buffers) ----
        const int ebase_r = tile * 128 + wm * 64 + (lane >> 2);
        const int ebase_c = wn * 32 + (lane & 3) * 2;
#pragma unroll
        for (int mt = 0; mt < 4; mt++) {
#pragma unroll
            for (int nt = 0; nt < 4; nt++) {
                const int c = ebase_c + nt * 8;
                const float b0 = sbias[c], b1 = sbias[c + 1];
#pragma unroll
                for (int half = 0; half < 2; half++) {
                    int r = ebase_r + mt * 16 + half * 8;
                    if (r < NDST) {
                        float o0 = fmaxf(acc[mt][nt][half * 2 + 0] + b0, 0.f);
                        float o1 = fmaxf(acc[mt][nt][half * 2 + 1] + b1, 0.f);
                        if (layer == 1) {
                            *(float2*)&outf[(size_t)r * DIM + c] = make_float2(o0, o1);
                        } else {
                            uint32_t h, l;
                            split2(o0, o1, h, l);
                            *(uint32_t*)&Oh[(size_t)r * DIM + c] = h;
                            *(uint32_t*)&Ol[(size_t)r * DIM + c] = l;
                        }
                    }
                }
            }
        }
    }
}

// ---------------------------------------------------------------------------
// Launch
// ---------------------------------------------------------------------------
extern "C" void kernel_launch(void* const* d_in, const int* in_sizes, int n_in,
                              void* d_out, int out_size)
{
    const float* x_src = (const float*)d_in[0];
    const float* x_dst = (const float*)d_in[1];
    const int*   e_src = (const int*)  d_in[2];
    const int*   e_dst = (const int*)  d_in[3];
    const float* Wss   = (const float*)d_in[4];
    const float* Wsn   = (const float*)d_in[5];
    const float* bsh   = (const float*)d_in[6];
    const float* Wrs   = (const float*)d_in[7];
    const float* Wrn   = (const float*)d_in[8];
    const float* brv   = (const float*)d_in[9];
    float* out = (float*)d_out;

    cudaFuncSetAttribute(k_gemm, cudaFuncAttributeMaxDynamicSharedMemorySize, SM_TOTAL);

    // Fused prologue (prep_X + zero_cnt + prep_B) then CSR chain
    k_prep<<<PREPX_BLKS + ZERO_BLKS + PREPB_BLKS, 256>>>(x_src, x_dst, Wss, Wsn, Wrs, Wrn);
    k_count<<<(NE / 2 + 255) / 256, 256>>>(e_src, e_dst);
    k_blocksum<<<dim3(SCAN_BLK, 2), 256>>>();
    k_write_off<<<dim3(SCAN_BLK, 2), 256>>>();
    k_place<<<(NE + 255) / 256, 256>>>(e_src, e_dst);

    for (int layer = 0; layer < NLAY; layer++) {
        k_gather<<<(2 * NDST * 32 + 255) / 256, 256>>>(layer, x_src, x_dst);
        k_gemm<<<dim3(PCTAS, 2), 256, SM_TOTAL>>>(layer, bsh, brv, out);
    }
}

// round 9
// speedup vs baseline: 1.0360x; 1.0360x over previous
#include <cuda_runtime.h>
#include <cuda_bf16.h>
#include <cstdint>

// Problem constants
#define NSRC 100000
#define NDST 100000
#define NE   500000
#define DIM  128
#define NLAY 2
#define TILES 782            // ceil(100000/128)
#define PCTAS 74             // persistent CTAs per direction GEMM
#define SCAN_BLK 98          // ceil(100000/1024)

// ---------------------------------------------------------------------------
// Scratch (device globals: allocation-free, graph-capture safe)
// ---------------------------------------------------------------------------
__device__ __nv_bfloat16 g_xs_hi[NSRC * DIM], g_xs_lo[NSRC * DIM];
__device__ __nv_bfloat16 g_xd_hi[NDST * DIM], g_xd_lo[NDST * DIM];
__device__ __nv_bfloat16 g_hs_hi[NSRC * DIM], g_hs_lo[NSRC * DIM];
__device__ __nv_bfloat16 g_hd_hi[NDST * DIM], g_hd_lo[NDST * DIM];
__device__ __nv_bfloat16 g_aggs_hi[NSRC * DIM], g_aggs_lo[NSRC * DIM];
__device__ __nv_bfloat16 g_aggd_hi[NDST * DIM], g_aggd_lo[NDST * DIM];
// CSR structures
__device__ int g_off_d[NDST + 1];
__device__ int g_off_s[NSRC + 1];
__device__ int g_cur_d[NDST];
__device__ int g_cur_s[NSRC];
__device__ int g_adj_d[NE];
__device__ int g_adj_s[NE];
__device__ int g_part[2][128];
// bf16 hi/lo weight images: [layer][dir][hi/lo][n=128][k=256]
__device__ __nv_bfloat16 g_Bbf[NLAY][2][2][DIM * 256];

// ---------------------------------------------------------------------------
__device__ __forceinline__ void split2(float x, float y, uint32_t& h, uint32_t& l) {
    asm("cvt.rn.bf16x2.f32 %0, %1, %2;" : "=r"(h) : "f"(y), "f"(x));
    float hx = __uint_as_float(h << 16), hy = __uint_as_float(h & 0xffff0000u);
    asm("cvt.rn.bf16x2.f32 %0, %1, %2;" : "=r"(l) : "f"(y - hy), "f"(x - hx));
}

// ---------------------------------------------------------------------------
// Prep kernels (stream B)
// ---------------------------------------------------------------------------
__global__ void k_prep_X(const float* __restrict__ xs, const float* __restrict__ xd) {
    int i = blockIdx.x * blockDim.x + threadIdx.x;   // float4 index
    const int n4 = NSRC * DIM / 4;
    if (i >= n4) return;
    float4 v = __ldg((const float4*)xs + i);
    uint32_t h0, h1, l0, l1;
    split2(v.x, v.y, h0, l0); split2(v.z, v.w, h1, l1);
    *(uint2*)&g_xs_hi[i * 4] = make_uint2(h0, h1);
    *(uint2*)&g_xs_lo[i * 4] = make_uint2(l0, l1);
    v = __ldg((const float4*)xd + i);
    split2(v.x, v.y, h0, l0); split2(v.z, v.w, h1, l1);
    *(uint2*)&g_xd_hi[i * 4] = make_uint2(h0, h1);
    *(uint2*)&g_xd_lo[i * 4] = make_uint2(l0, l1);
}
__global__ void k_prep_B(const float* __restrict__ Wss, const float* __restrict__ Wsn,
                         const float* __restrict__ Wrs, const float* __restrict__ Wrn) {
    int l = blockIdx.x >> 1, d = blockIdx.x & 1;
    const float* Wself  = (d == 0 ? Wss : Wrs) + l * DIM * DIM;
    const float* Wneigh = (d == 0 ? Wsn : Wrn) + l * DIM * DIM;
    for (int i = blockIdx.y * blockDim.x + threadIdx.x; i < DIM * 256; i += blockDim.x * gridDim.y) {
        int n = i >> 8;
        int k = i & 255;
        float v = (k < DIM) ? __ldg(&Wself[n * DIM + k]) : __ldg(&Wneigh[n * DIM + (k - DIM)]);
        __nv_bfloat16 hi = __float2bfloat16(v);
        __nv_bfloat16 lo = __float2bfloat16(v - __bfloat162float(hi));
        g_Bbf[l][d][0][i] = hi;
        g_Bbf[l][d][1][i] = lo;
    }
}

// ---------------------------------------------------------------------------
// CSR build (origin stream)
// ---------------------------------------------------------------------------
__global__ void k_zero_cnt() {
    int i = blockIdx.x * blockDim.x + threadIdx.x;
    if (i < NDST) { g_cur_d[i] = 0; g_cur_s[i] = 0; }
}
__global__ void k_count(const int* __restrict__ es, const int* __restrict__ ed) {
    int i = blockIdx.x * blockDim.x + threadIdx.x;   // pair index
    if (i * 2 + 1 < NE) {
        int2 e2 = __ldg((const int2*)ed + i);
        int2 s2 = __ldg((const int2*)es + i);
        atomicAdd(&g_cur_d[e2.x], 1);
        atomicAdd(&g_cur_d[e2.y], 1);
        atomicAdd(&g_cur_s[s2.x], 1);
        atomicAdd(&g_cur_s[s2.y], 1);
    } else if (i * 2 < NE) {
        atomicAdd(&g_cur_d[__ldg(&ed[i * 2])], 1);
        atomicAdd(&g_cur_s[__ldg(&es[i * 2])], 1);
    }
}
__global__ void k_blocksum() {
    const int a = blockIdx.y;
    const int* cnt = a ? g_cur_s : g_cur_d;
    __shared__ int sm[256];
    int base = blockIdx.x * 1024 + threadIdx.x * 4;
    int s = 0;
#pragma unroll
    for (int q = 0; q < 4; q++) { int i = base + q; if (i < NDST) s += cnt[i]; }
    sm[threadIdx.x] = s; __syncthreads();
    for (int st = 128; st > 0; st >>= 1) {
        if (threadIdx.x < st) sm[threadIdx.x] += sm[threadIdx.x + st];
        __syncthreads();
    }
    if (threadIdx.x == 0) g_part[a][blockIdx.x] = sm[0];
}
__global__ void k_write_off() {
    const int a = blockIdx.y;
    int* cnt = a ? g_cur_s : g_cur_d;
    int* off = a ? g_off_s : g_off_d;
    __shared__ int sm[256];
    __shared__ int s_pre;
    const int t = threadIdx.x;
    if (t == 0) {
        int p = 0;
        for (int b2 = 0; b2 < blockIdx.x; b2++) p += __ldg(&g_part[a][b2]);
        s_pre = p;
    }
    const int i0 = blockIdx.x * 1024 + t * 4;
    int c[4]; int ts = 0;
#pragma unroll
    for (int q = 0; q < 4; q++) { int i = i0 + q; c[q] = (i < NDST) ? cnt[i] : 0; ts += c[q]; }
    sm[t] = ts; __syncthreads();
    for (int st = 1; st < 256; st <<= 1) {
        int u = (t >= st) ? sm[t - st] : 0;
        __syncthreads();
        sm[t] += u;
        __syncthreads();
    }
    int excl = sm[t] - ts + s_pre;
#pragma unroll
    for (int q = 0; q < 4; q++) {
        int i = i0 + q;
        if (i < NDST) {
            off[i] = excl;
            cnt[i] = excl;
            if (i == NDST - 1) off[NDST] = excl + c[q];
            excl += c[q];
        }
    }
}
__global__ void k_place(const int* __restrict__ es, const int* __restrict__ ed) {
    int i = blockIdx.x * blockDim.x + threadIdx.x;
    if (i >= NE) return;
    int s = __ldg(&es[i]), d = __ldg(&ed[i]);
    int pd = atomicAdd(&g_cur_d[d], 1);
    g_adj_d[pd] = s;
    int ps = atomicAdd(&g_cur_s[s], 1);
    g_adj_s[ps] = d;
}

// ---------------------------------------------------------------------------
// CSR gather, single direction per launch. Mean folded in; bf16 hi/lo output.
// dir=0: agg into dst side;  dir=1: agg into src side.
// ---------------------------------------------------------------------------
__device__ __forceinline__ void acc_bf4(float4& acc, uint2 H, uint2 L) {
    float2 fh0 = __bfloat1622float2(*(__nv_bfloat162*)&H.x);
    float2 fh1 = __bfloat1622float2(*(__nv_bfloat162*)&H.y);
    float2 fl0 = __bfloat1622float2(*(__nv_bfloat162*)&L.x);
    float2 fl1 = __bfloat1622float2(*(__nv_bfloat162*)&L.y);
    acc.x += fh0.x + fl0.x; acc.y += fh0.y + fl0.y;
    acc.z += fh1.x + fl1.x; acc.w += fh1.y + fl1.y;
}

__global__ void __launch_bounds__(256) k_gather(
    int layer, int dir, const float* __restrict__ xs, const float* __restrict__ xd)
{
    int node = (blockIdx.x * blockDim.x + threadIdx.x) >> 5;
    if (node >= NDST) return;
    const int lane = threadIdx.x & 31;

    const int *off, *adj; const float* featf;
    const __nv_bfloat16 *fh, *fl;
    __nv_bfloat16 *oh, *ol;
    if (dir == 0) {
        off = g_off_d; adj = g_adj_d;
        featf = xs; fh = g_hs_hi; fl = g_hs_lo;
        oh = g_aggd_hi; ol = g_aggd_lo;
    } else {
        off = g_off_s; adj = g_adj_s;
        featf = xd; fh = g_hd_hi; fl = g_hd_lo;
        oh = g_aggs_hi; ol = g_aggs_lo;
    }

    const int b = off[node], e = off[node + 1];
    const int c = lane * 4;
    float4 acc = make_float4(0.f, 0.f, 0.f, 0.f);
    if (layer == 0) {
        int j = b;
        for (; j + 3 < e; j += 4) {
            int r0 = __ldg(&adj[j]);
            int r1 = __ldg(&adj[j + 1]);
            int r2 = __ldg(&adj[j + 2]);
            int r3 = __ldg(&adj[j + 3]);
            float4 v0 = __ldg((const float4*)&featf[(size_t)r0 * DIM + c]);
            float4 v1 = __ldg((const float4*)&featf[(size_t)r1 * DIM + c]);
            float4 v2 = __ldg((const float4*)&featf[(size_t)r2 * DIM + c]);
            float4 v3 = __ldg((const float4*)&featf[(size_t)r3 * DIM + c]);
            acc.x += (v0.x + v1.x) + (v2.x + v3.x);
            acc.y += (v0.y + v1.y) + (v2.y + v3.y);
            acc.z += (v0.z + v1.z) + (v2.z + v3.z);
            acc.w += (v0.w + v1.w) + (v2.w + v3.w);
        }
        for (; j < e; j++) {
            int r0 = __ldg(&adj[j]);
            float4 v0 = __ldg((const float4*)&featf[(size_t)r0 * DIM + c]);
            acc.x += v0.x; acc.y += v0.y; acc.z += v0.z; acc.w += v0.w;
        }
    } else {
        int j = b;
        for (; j + 1 < e; j += 2) {
            int r0 = __ldg(&adj[j]);
            int r1 = __ldg(&adj[j + 1]);
            uint2 H0 = __ldg((const uint2*)&fh[(size_t)r0 * DIM + c]);
            uint2 L0 = __ldg((const uint2*)&fl[(size_t)r0 * DIM + c]);
            uint2 H1 = __ldg((const uint2*)&fh[(size_t)r1 * DIM + c]);
            uint2 L1 = __ldg((const uint2*)&fl[(size_t)r1 * DIM + c]);
            acc_bf4(acc, H0, L0);
            acc_bf4(acc, H1, L1);
        }
        if (j < e) {
            int r0 = __ldg(&adj[j]);
            uint2 H0 = __ldg((const uint2*)&fh[(size_t)r0 * DIM + c]);
            uint2 L0 = __ldg((const uint2*)&fl[(size_t)r0 * DIM + c]);
            acc_bf4(acc, H0, L0);
        }
    }
    const float s = 1.0f / fmaxf((float)(e - b), 1.0f);
    acc.x *= s; acc.y *= s; acc.z *= s; acc.w *= s;

    uint32_t h0, h1, l0, l1;
    split2(acc.x, acc.y, h0, l0);
    split2(acc.z, acc.w, h1, l1);
    *(uint2*)&oh[(size_t)node * DIM + c] = make_uint2(h0, h1);
    *(uint2*)&ol[(size_t)node * DIM + c] = make_uint2(l0, l1);
}

// ---------------------------------------------------------------------------
// Persistent pipelined mma.sync GEMM (3-term hi/lo, unique fragments),
// single direction per launch (74 CTAs). R6-style pipeline (measured fastest).
// ---------------------------------------------------------------------------
#define SPAD 72
#define PLANE_B 18432
#define AREG_B 73728
#define BREG_B 147456
#define SM_BIAS_B (AREG_B + BREG_B)
#define SM_TOTAL (SM_BIAS_B + 512)

__device__ __forceinline__ uint32_t smem_u32(const void* p) {
    uint32_t a;
    asm("{ .reg .u64 t; cvta.to.shared.u64 t, %1; cvt.u32.u64 %0, t; }" : "=r"(a) : "l"(p));
    return a;
}
#define CP_ASYNC16(dst, src) \
    asm volatile("cp.async.cg.shared.global [%0], [%1], 16;" :: "r"(dst), "l"(src))
#define CP_COMMIT() asm volatile("cp.async.commit_group;")
#define CP_WAIT1()  asm volatile("cp.async.wait_group 1;")

#define LDSM_X4(r, addr) \
    asm volatile("ldmatrix.sync.aligned.m8n8.x4.shared.b16 {%0,%1,%2,%3}, [%4];" \
        : "=r"((r)[0]), "=r"((r)[1]), "=r"((r)[2]), "=r"((r)[3]) : "r"(addr))

#define MMA_BF16(c, a, b0, b1) \
    asm volatile("mma.sync.aligned.m16n8k16.row.col.f32.bf16.bf16.f32 " \
        "{%0,%1,%2,%3}, {%4,%5,%6,%7}, {%8,%9}, {%0,%1,%2,%3};" \
        : "+f"((c)[0]), "+f"((c)[1]), "+f"((c)[2]), "+f"((c)[3]) \
        : "r"((a)[0]), "r"((a)[1]), "r"((a)[2]), "r"((a)[3]), "r"(b0), "r"(b1))

__global__ void __launch_bounds__(256, 1) k_gemm(
    int layer, int dir, const float* __restrict__ bsh, const float* __restrict__ brv,
    float* __restrict__ dout)
{
    extern __shared__ unsigned char smraw[];
    __nv_bfloat16* sm = (__nv_bfloat16*)smraw;
    float* sbias = (float*)(smraw + SM_BIAS_B);

    const int tid  = threadIdx.x;
    const int wid  = tid >> 5, lane = tid & 31;
    const int wm   = wid & 1;
    const int wn   = wid >> 1;
    const uint32_t smb = smem_u32(sm);

    const float* bias;
    const __nv_bfloat16 *Sh, *Sl, *Gh, *Gl;
    __nv_bfloat16 *Oh, *Ol;
    float* outf;
    if (dir == 0) {
        Sh = layer ? g_hd_hi : g_xd_hi;  Sl = layer ? g_hd_lo : g_xd_lo;
        Gh = g_aggd_hi; Gl = g_aggd_lo;
        Oh = g_hd_hi; Ol = g_hd_lo;
        bias = bsh + layer * DIM;
        outf = dout + (size_t)NSRC * DIM;
    } else {
        Sh = layer ? g_hs_hi : g_xs_hi;  Sl = layer ? g_hs_lo : g_xs_lo;
        Gh = g_aggs_hi; Gl = g_aggs_lo;
        Oh = g_hs_hi; Ol = g_hs_lo;
        bias = brv + layer * DIM;
        outf = dout;
    }
    const __nv_bfloat16* Bhg = g_Bbf[layer][dir][0];
    const __nv_bfloat16* Blg = g_Bbf[layer][dir][1];

    // ---- B: all 4 chunks hi/lo via cp.async, one group ----
#pragma unroll 4
    for (int j = 0; j < 32; j++) {
        int i = j * 256 + tid;
        int pc = i >> 10;
        int cch = pc >> 1, pp = pc & 1;
        int rem = i & 1023;
        int rowi = rem >> 3, piece = rem & 7;
        const __nv_bfloat16* src = (pp ? Blg : Bhg) + rowi * 256 + cch * 64 + piece * 8;
        uint32_t dst = smb + AREG_B + pc * PLANE_B + rowi * 144 + piece * 16;
        CP_ASYNC16(dst, src);
    }
    CP_COMMIT();
    if (tid < DIM) sbias[tid] = bias[tid];

    const int a_row_off = (wm * 64 + (lane & 15)) * SPAD + (lane >> 4) * 8;
    const int b_row_off = (wn * 32 + (lane & 7) + (lane >> 4) * 8) * SPAD + ((lane >> 3) & 1) * 8;

    auto issue_A = [&](int tile, int kc, int st) {
        const __nv_bfloat16* ph = (kc < 2) ? Sh : Gh;
        const __nv_bfloat16* pl = (kc < 2) ? Sl : Gl;
        const int col0 = (kc & 1) * 64;
#pragma unroll
        for (int j = 0; j < 8; j++) {
            int i = j * 256 + tid;
            int pp = i >> 10;
            int rem = i & 1023;
            int rowi = rem >> 3, piece = rem & 7;
            int r = tile * 128 + rowi; if (r > NDST - 1) r = NDST - 1;
            const __nv_bfloat16* src = (pp ? pl : ph) + (size_t)r * DIM + col0 + piece * 8;
            uint32_t dst = smb + (st * 2 + pp) * PLANE_B + rowi * 144 + piece * 16;
            CP_ASYNC16(dst, src);
        }
    };

    int st = 0;
    issue_A(blockIdx.x, 0, 0);
    CP_COMMIT();

    for (int tile = blockIdx.x; tile < TILES; tile += PCTAS) {
        float acc[4][4][4];
#pragma unroll
        for (int i = 0; i < 4; i++)
#pragma unroll
            for (int j = 0; j < 4; j++)
#pragma unroll
                for (int q = 0; q < 4; q++) acc[i][j][q] = 0.f;

#pragma unroll 1
        for (int kc = 0; kc < 4; kc++) {
            int ntile = (kc < 3) ? tile : tile + PCTAS;
            int nkc   = (kc < 3) ? kc + 1 : 0;
            if (ntile < TILES) issue_A(ntile, nkc, st ^ 1);
            CP_COMMIT();
            CP_WAIT1();
            __syncthreads();

            const uint32_t aHi = smb + (st * 2) * PLANE_B + 2 * a_row_off;
            const uint32_t aLo = aHi + PLANE_B;
            const uint32_t bHi = smb + AREG_B + (kc * 2) * PLANE_B + 2 * b_row_off;
            const uint32_t bLo = bHi + PLANE_B;
#pragma unroll
            for (int k16 = 0; k16 < 4; k16++) {
                uint32_t ah[4][4], al[4][4], bh[2][4], bl[2][4];
#pragma unroll
                for (int mt = 0; mt < 4; mt++) {
                    LDSM_X4(ah[mt], aHi + 2 * (mt * 16 * SPAD + k16 * 16));
                    LDSM_X4(al[mt], aLo + 2 * (mt * 16 * SPAD + k16 * 16));
                }
#pragma unroll
                for (int p = 0; p < 2; p++) {
                    LDSM_X4(bh[p], bHi + 2 * (p * 16 * SPAD + k16 * 16));
                    LDSM_X4(bl[p], bLo + 2 * (p * 16 * SPAD + k16 * 16));
                }
#pragma unroll
                for (int mt = 0; mt < 4; mt++)
#pragma unroll
                    for (int nt = 0; nt < 4; nt++) {
                        uint32_t* BH = &bh[nt >> 1][(nt & 1) * 2];
                        uint32_t* BL = &bl[nt >> 1][(nt & 1) * 2];
                        MMA_BF16(acc[mt][nt], ah[mt], BH[0], BH[1]);
                        MMA_BF16(acc[mt][nt], al[mt], BH[0], BH[1]);
                        MMA_BF16(acc[mt][nt], ah[mt], BL[0], BL[1]);
                    }
            }
            __syncthreads();
            st ^= 1;
        }

        // ---- epilogue ----
        const int ebase_r = tile * 128 + wm * 64 + (lane >> 2);
        const int ebase_c = wn * 32 + (lane & 3) * 2;
#pragma unroll
        for (int mt = 0; mt < 4; mt++) {
#pragma unroll
            for (int nt = 0; nt < 4; nt++) {
                const int c = ebase_c + nt * 8;
                const float b0 = sbias[c], b1 = sbias[c + 1];
#pragma unroll
                for (int half = 0; half < 2; half++) {
                    int r = ebase_r + mt * 16 + half * 8;
                    if (r < NDST) {
                        float o0 = fmaxf(acc[mt][nt][half * 2 + 0] + b0, 0.f);
                        float o1 = fmaxf(acc[mt][nt][half * 2 + 1] + b1, 0.f);
                        if (layer == 1) {
                            *(float2*)&outf[(size_t)r * DIM + c] = make_float2(o0, o1);
                        } else {
                            uint32_t h, l;
                            split2(o0, o1, h, l);
                            *(uint32_t*)&Oh[(size_t)r * DIM + c] = h;
                            *(uint32_t*)&Ol[(size_t)r * DIM + c] = l;
                        }
                    }
                }
            }
        }
    }
}

// ---------------------------------------------------------------------------
// Launch: fork/join DAG across two streams (capture-safe pattern)
// ---------------------------------------------------------------------------
struct HxCtx {
    cudaStream_t s2;
    cudaEvent_t evFork, evPrep, evCSR, evD0, evS0, evEnd;
    HxCtx() {
        cudaStreamCreateWithFlags(&s2, cudaStreamNonBlocking);
        cudaEventCreateWithFlags(&evFork, cudaEventDisableTiming);
        cudaEventCreateWithFlags(&evPrep, cudaEventDisableTiming);
        cudaEventCreateWithFlags(&evCSR,  cudaEventDisableTiming);
        cudaEventCreateWithFlags(&evD0,   cudaEventDisableTiming);
        cudaEventCreateWithFlags(&evS0,   cudaEventDisableTiming);
        cudaEventCreateWithFlags(&evEnd,  cudaEventDisableTiming);
    }
};

extern "C" void kernel_launch(void* const* d_in, const int* in_sizes, int n_in,
                              void* d_out, int out_size)
{
    const float* x_src = (const float*)d_in[0];
    const float* x_dst = (const float*)d_in[1];
    const int*   e_src = (const int*)  d_in[2];
    const int*   e_dst = (const int*)  d_in[3];
    const float* Wss   = (const float*)d_in[4];
    const float* Wsn   = (const float*)d_in[5];
    const float* bsh   = (const float*)d_in[6];
    const float* Wrs   = (const float*)d_in[7];
    const float* Wrn   = (const float*)d_in[8];
    const float* brv   = (const float*)d_in[9];
    float* out = (float*)d_out;

    static HxCtx C;   // streams/events created on first call (pre-capture)
    cudaFuncSetAttribute(k_gemm, cudaFuncAttributeMaxDynamicSharedMemorySize, SM_TOTAL);

    // fork
    cudaEventRecord(C.evFork, 0);
    cudaStreamWaitEvent(C.s2, C.evFork, 0);

    // stream B: weight/feature prep (independent of CSR)
    k_prep_B<<<dim3(4, 8), 256, 0, C.s2>>>(Wss, Wsn, Wrs, Wrn);
    k_prep_X<<<(NSRC * DIM / 4 + 255) / 256, 256, 0, C.s2>>>(x_src, x_dst);
    cudaEventRecord(C.evPrep, C.s2);

    // origin: CSR build
    k_zero_cnt<<<(NDST + 255) / 256, 256>>>();
    k_count<<<(NE / 2 + 255) / 256, 256>>>(e_src, e_dst);
    k_blocksum<<<dim3(SCAN_BLK, 2), 256>>>();
    k_write_off<<<dim3(SCAN_BLK, 2), 256>>>();
    k_place<<<(NE + 255) / 256, 256>>>(e_src, e_dst);
    cudaEventRecord(C.evCSR, 0);
    cudaStreamWaitEvent(C.s2, C.evCSR, 0);

    const int GATH_BLKS = (NDST * 32 + 255) / 256;

    // chain B (s2): gth_s0 -> gemm_s0 -> gth_d1 -> gemm_d1
    k_gather<<<GATH_BLKS, 256, 0, C.s2>>>(0, 1, x_src, x_dst);
    k_gemm<<<PCTAS, 256, SM_TOTAL, C.s2>>>(0, 1, bsh, brv, out);   // writes g_hs
    cudaEventRecord(C.evS0, C.s2);
    k_gather<<<GATH_BLKS, 256, 0, C.s2>>>(1, 0, x_src, x_dst);     // reads g_hs

    // chain A (origin): gth_d0 -> gemm_d0 -> gth_s1 -> gemm_s1
    k_gather<<<GATH_BLKS, 256>>>(0, 0, x_src, x_dst);
    cudaStreamWaitEvent(0, C.evPrep, 0);                           // need planes + B images
    k_gemm<<<PCTAS, 256, SM_TOTAL>>>(0, 0, bsh, brv, out);         // writes g_hd
    cudaEventRecord(C.evD0, 0);
    k_gather<<<GATH_BLKS, 256>>>(1, 1, x_src, x_dst);              // reads g_hd
    cudaStreamWaitEvent(0, C.evS0, 0);                             // self term needs g_hs
    k_gemm<<<PCTAS, 256, SM_TOTAL>>>(1, 1, bsh, brv, out);         // writes dout h_s half

    // chain B tail: gemm_d1 needs g_hd (evD0)
    cudaStreamWaitEvent(C.s2, C.evD0, 0);
    k_gemm<<<PCTAS, 256, SM_TOTAL, C.s2>>>(1, 0, bsh, brv, out);   // writes dout h_d half
    cudaEventRecord(C.evEnd, C.s2);
    cudaStreamWaitEvent(0, C.evEnd, 0);                            // join
}

// round 10
// speedup vs baseline: 1.1141x; 1.0755x over previous
#include <cuda_runtime.h>
#include <cuda_bf16.h>
#include <cstdint>

// Problem constants
#define NSRC 100000
#define NDST 100000
#define NE   500000
#define DIM  128
#define NLAY 2
#define TILES 782            // ceil(100000/128)
#define PCTAS 74             // persistent CTAs per direction GEMM
#define SCAN_BLK 98          // ceil(100000/1024)

// ---------------------------------------------------------------------------
// Scratch (device globals: allocation-free, graph-capture safe)
// ---------------------------------------------------------------------------
__device__ __nv_bfloat16 g_xs_hi[NSRC * DIM], g_xs_lo[NSRC * DIM];
__device__ __nv_bfloat16 g_xd_hi[NDST * DIM], g_xd_lo[NDST * DIM];
__device__ __nv_bfloat16 g_hs_hi[NSRC * DIM], g_hs_lo[NSRC * DIM];
__device__ __nv_bfloat16 g_hd_hi[NDST * DIM], g_hd_lo[NDST * DIM];
// agg planes double-buffered by LAYER: removes WAR between layer-1 gathers
// and layer-0 GEMM reads (they now touch different buffers).
__device__ __nv_bfloat16 g_aggs_hi[NLAY][NSRC * DIM], g_aggs_lo[NLAY][NSRC * DIM];
__device__ __nv_bfloat16 g_aggd_hi[NLAY][NDST * DIM], g_aggd_lo[NLAY][NDST * DIM];
// CSR structures
__device__ int g_off_d[NDST + 1];
__device__ int g_off_s[NSRC + 1];
__device__ int g_cur_d[NDST];
__device__ int g_cur_s[NSRC];
__device__ int g_adj_d[NE];
__device__ int g_adj_s[NE];
__device__ int g_part[2][128];
// bf16 hi/lo weight images: [layer][dir][hi/lo][n=128][k=256]
__device__ __nv_bfloat16 g_Bbf[NLAY][2][2][DIM * 256];

// ---------------------------------------------------------------------------
__device__ __forceinline__ void split2(float x, float y, uint32_t& h, uint32_t& l) {
    asm("cvt.rn.bf16x2.f32 %0, %1, %2;" : "=r"(h) : "f"(y), "f"(x));
    float hx = __uint_as_float(h << 16), hy = __uint_as_float(h & 0xffff0000u);
    asm("cvt.rn.bf16x2.f32 %0, %1, %2;" : "=r"(l) : "f"(y - hy), "f"(x - hx));
}

// ---------------------------------------------------------------------------
// Prep kernels (stream B)
// ---------------------------------------------------------------------------
__global__ void k_prep_X(const float* __restrict__ xs, const float* __restrict__ xd) {
    int i = blockIdx.x * blockDim.x + threadIdx.x;   // float4 index
    const int n4 = NSRC * DIM / 4;
    if (i >= n4) return;
    float4 v = __ldg((const float4*)xs + i);
    uint32_t h0, h1, l0, l1;
    split2(v.x, v.y, h0, l0); split2(v.z, v.w, h1, l1);
    *(uint2*)&g_xs_hi[i * 4] = make_uint2(h0, h1);
    *(uint2*)&g_xs_lo[i * 4] = make_uint2(l0, l1);
    v = __ldg((const float4*)xd + i);
    split2(v.x, v.y, h0, l0); split2(v.z, v.w, h1, l1);
    *(uint2*)&g_xd_hi[i * 4] = make_uint2(h0, h1);
    *(uint2*)&g_xd_lo[i * 4] = make_uint2(l0, l1);
}
__global__ void k_prep_B(const float* __restrict__ Wss, const float* __restrict__ Wsn,
                         const float* __restrict__ Wrs, const float* __restrict__ Wrn) {
    int l = blockIdx.x >> 1, d = blockIdx.x & 1;
    const float* Wself  = (d == 0 ? Wss : Wrs) + l * DIM * DIM;
    const float* Wneigh = (d == 0 ? Wsn : Wrn) + l * DIM * DIM;
    for (int i = blockIdx.y * blockDim.x + threadIdx.x; i < DIM * 256; i += blockDim.x * gridDim.y) {
        int n = i >> 8;
        int k = i & 255;
        float v = (k < DIM) ? __ldg(&Wself[n * DIM + k]) : __ldg(&Wneigh[n * DIM + (k - DIM)]);
        __nv_bfloat16 hi = __float2bfloat16(v);
        __nv_bfloat16 lo = __float2bfloat16(v - __bfloat162float(hi));
        g_Bbf[l][d][0][i] = hi;
        g_Bbf[l][d][1][i] = lo;
    }
}

// ---------------------------------------------------------------------------
// CSR build (origin stream)
// ---------------------------------------------------------------------------
__global__ void k_zero_cnt() {
    int i = blockIdx.x * blockDim.x + threadIdx.x;
    if (i < NDST) { g_cur_d[i] = 0; g_cur_s[i] = 0; }
}
__global__ void k_count(const int* __restrict__ es, const int* __restrict__ ed) {
    int i = blockIdx.x * blockDim.x + threadIdx.x;   // pair index
    if (i * 2 + 1 < NE) {
        int2 e2 = __ldg((const int2*)ed + i);
        int2 s2 = __ldg((const int2*)es + i);
        atomicAdd(&g_cur_d[e2.x], 1);
        atomicAdd(&g_cur_d[e2.y], 1);
        atomicAdd(&g_cur_s[s2.x], 1);
        atomicAdd(&g_cur_s[s2.y], 1);
    } else if (i * 2 < NE) {
        atomicAdd(&g_cur_d[__ldg(&ed[i * 2])], 1);
        atomicAdd(&g_cur_s[__ldg(&es[i * 2])], 1);
    }
}
__global__ void k_blocksum() {
    const int a = blockIdx.y;
    const int* cnt = a ? g_cur_s : g_cur_d;
    __shared__ int sm[256];
    int base = blockIdx.x * 1024 + threadIdx.x * 4;
    int s = 0;
#pragma unroll
    for (int q = 0; q < 4; q++) { int i = base + q; if (i < NDST) s += cnt[i]; }
    sm[threadIdx.x] = s; __syncthreads();
    for (int st = 128; st > 0; st >>= 1) {
        if (threadIdx.x < st) sm[threadIdx.x] += sm[threadIdx.x + st];
        __syncthreads();
    }
    if (threadIdx.x == 0) g_part[a][blockIdx.x] = sm[0];
}
__global__ void k_write_off() {
    const int a = blockIdx.y;
    int* cnt = a ? g_cur_s : g_cur_d;
    int* off = a ? g_off_s : g_off_d;
    __shared__ int sm[256];
    __shared__ int s_pre;
    const int t = threadIdx.x;
    if (t == 0) {
        int p = 0;
        for (int b2 = 0; b2 < blockIdx.x; b2++) p += __ldg(&g_part[a][b2]);
        s_pre = p;
    }
    const int i0 = blockIdx.x * 1024 + t * 4;
    int c[4]; int ts = 0;
#pragma unroll
    for (int q = 0; q < 4; q++) { int i = i0 + q; c[q] = (i < NDST) ? cnt[i] : 0; ts += c[q]; }
    sm[t] = ts; __syncthreads();
    for (int st = 1; st < 256; st <<= 1) {
        int u = (t >= st) ? sm[t - st] : 0;
        __syncthreads();
        sm[t] += u;
        __syncthreads();
    }
    int excl = sm[t] - ts + s_pre;
#pragma unroll
    for (int q = 0; q < 4; q++) {
        int i = i0 + q;
        if (i < NDST) {
            off[i] = excl;
            cnt[i] = excl;
            if (i == NDST - 1) off[NDST] = excl + c[q];
            excl += c[q];
        }
    }
}
__global__ void k_place(const int* __restrict__ es, const int* __restrict__ ed) {
    int i = blockIdx.x * blockDim.x + threadIdx.x;
    if (i >= NE) return;
    int s = __ldg(&es[i]), d = __ldg(&ed[i]);
    int pd = atomicAdd(&g_cur_d[d], 1);
    g_adj_d[pd] = s;
    int ps = atomicAdd(&g_cur_s[s], 1);
    g_adj_s[ps] = d;
}

// ---------------------------------------------------------------------------
// CSR gather, single direction per launch, layer-indexed agg output buffers.
// ---------------------------------------------------------------------------
__device__ __forceinline__ void acc_bf4(float4& acc, uint2 H, uint2 L) {
    float2 fh0 = __bfloat1622float2(*(__nv_bfloat162*)&H.x);
    float2 fh1 = __bfloat1622float2(*(__nv_bfloat162*)&H.y);
    float2 fl0 = __bfloat1622float2(*(__nv_bfloat162*)&L.x);
    float2 fl1 = __bfloat1622float2(*(__nv_bfloat162*)&L.y);
    acc.x += fh0.x + fl0.x; acc.y += fh0.y + fl0.y;
    acc.z += fh1.x + fl1.x; acc.w += fh1.y + fl1.y;
}

__global__ void __launch_bounds__(256) k_gather(
    int layer, int dir, const float* __restrict__ xs, const float* __restrict__ xd)
{
    int node = (blockIdx.x * blockDim.x + threadIdx.x) >> 5;
    if (node >= NDST) return;
    const int lane = threadIdx.x & 31;

    const int *off, *adj; const float* featf;
    const __nv_bfloat16 *fh, *fl;
    __nv_bfloat16 *oh, *ol;
    if (dir == 0) {
        off = g_off_d; adj = g_adj_d;
        featf = xs; fh = g_hs_hi; fl = g_hs_lo;
        oh = g_aggd_hi[layer]; ol = g_aggd_lo[layer];
    } else {
        off = g_off_s; adj = g_adj_s;
        featf = xd; fh = g_hd_hi; fl = g_hd_lo;
        oh = g_aggs_hi[layer]; ol = g_aggs_lo[layer];
    }

    const int b = off[node], e = off[node + 1];
    const int c = lane * 4;
    float4 acc = make_float4(0.f, 0.f, 0.f, 0.f);
    if (layer == 0) {
        int j = b;
        for (; j + 3 < e; j += 4) {
            int r0 = __ldg(&adj[j]);
            int r1 = __ldg(&adj[j + 1]);
            int r2 = __ldg(&adj[j + 2]);
            int r3 = __ldg(&adj[j + 3]);
            float4 v0 = __ldg((const float4*)&featf[(size_t)r0 * DIM + c]);
            float4 v1 = __ldg((const float4*)&featf[(size_t)r1 * DIM + c]);
            float4 v2 = __ldg((const float4*)&featf[(size_t)r2 * DIM + c]);
            float4 v3 = __ldg((const float4*)&featf[(size_t)r3 * DIM + c]);
            acc.x += (v0.x + v1.x) + (v2.x + v3.x);
            acc.y += (v0.y + v1.y) + (v2.y + v3.y);
            acc.z += (v0.z + v1.z) + (v2.z + v3.z);
            acc.w += (v0.w + v1.w) + (v2.w + v3.w);
        }
        for (; j < e; j++) {
            int r0 = __ldg(&adj[j]);
            float4 v0 = __ldg((const float4*)&featf[(size_t)r0 * DIM + c]);
            acc.x += v0.x; acc.y += v0.y; acc.z += v0.z; acc.w += v0.w;
        }
    } else {
        int j = b;
        for (; j + 2 < e; j += 3) {                    // 6 loads in flight
            int r0 = __ldg(&adj[j]);
            int r1 = __ldg(&adj[j + 1]);
            int r2 = __ldg(&adj[j + 2]);
            uint2 H0 = __ldg((const uint2*)&fh[(size_t)r0 * DIM + c]);
            uint2 L0 = __ldg((const uint2*)&fl[(size_t)r0 * DIM + c]);
            uint2 H1 = __ldg((const uint2*)&fh[(size_t)r1 * DIM + c]);
            uint2 L1 = __ldg((const uint2*)&fl[(size_t)r1 * DIM + c]);
            uint2 H2 = __ldg((const uint2*)&fh[(size_t)r2 * DIM + c]);
            uint2 L2 = __ldg((const uint2*)&fl[(size_t)r2 * DIM + c]);
            acc_bf4(acc, H0, L0);
            acc_bf4(acc, H1, L1);
            acc_bf4(acc, H2, L2);
        }
        for (; j < e; j++) {
            int r0 = __ldg(&adj[j]);
            uint2 H0 = __ldg((const uint2*)&fh[(size_t)r0 * DIM + c]);
            uint2 L0 = __ldg((const uint2*)&fl[(size_t)r0 * DIM + c]);
            acc_bf4(acc, H0, L0);
        }
    }
    const float s = 1.0f / fmaxf((float)(e - b), 1.0f);
    acc.x *= s; acc.y *= s; acc.z *= s; acc.w *= s;

    uint32_t h0, h1, l0, l1;
    split2(acc.x, acc.y, h0, l0);
    split2(acc.z, acc.w, h1, l1);
    *(uint2*)&oh[(size_t)node * DIM + c] = make_uint2(h0, h1);
    *(uint2*)&ol[(size_t)node * DIM + c] = make_uint2(l0, l1);
}

// ---------------------------------------------------------------------------
// Persistent pipelined mma.sync GEMM (3-term hi/lo, unique fragments),
// single direction per launch (74 CTAs). R6-style pipeline (measured fastest).
// ---------------------------------------------------------------------------
#define SPAD 72
#define PLANE_B 18432
#define AREG_B 73728
#define BREG_B 147456
#define SM_BIAS_B (AREG_B + BREG_B)
#define SM_TOTAL (SM_BIAS_B + 512)

__device__ __forceinline__ uint32_t smem_u32(const void* p) {
    uint32_t a;
    asm("{ .reg .u64 t; cvta.to.shared.u64 t, %1; cvt.u32.u64 %0, t; }" : "=r"(a) : "l"(p));
    return a;
}
#define CP_ASYNC16(dst, src) \
    asm volatile("cp.async.cg.shared.global [%0], [%1], 16;" :: "r"(dst), "l"(src))
#define CP_COMMIT() asm volatile("cp.async.commit_group;")
#define CP_WAIT1()  asm volatile("cp.async.wait_group 1;")

#define LDSM_X4(r, addr) \
    asm volatile("ldmatrix.sync.aligned.m8n8.x4.shared.b16 {%0,%1,%2,%3}, [%4];" \
        : "=r"((r)[0]), "=r"((r)[1]), "=r"((r)[2]), "=r"((r)[3]) : "r"(addr))

#define MMA_BF16(c, a, b0, b1) \
    asm volatile("mma.sync.aligned.m16n8k16.row.col.f32.bf16.bf16.f32 " \
        "{%0,%1,%2,%3}, {%4,%5,%6,%7}, {%8,%9}, {%0,%1,%2,%3};" \
        : "+f"((c)[0]), "+f"((c)[1]), "+f"((c)[2]), "+f"((c)[3]) \
        : "r"((a)[0]), "r"((a)[1]), "r"((a)[2]), "r"((a)[3]), "r"(b0), "r"(b1))

__global__ void __launch_bounds__(256, 1) k_gemm(
    int layer, int dir, const float* __restrict__ bsh, const float* __restrict__ brv,
    float* __restrict__ dout)
{
    extern __shared__ unsigned char smraw[];
    __nv_bfloat16* sm = (__nv_bfloat16*)smraw;
    float* sbias = (float*)(smraw + SM_BIAS_B);

    const int tid  = threadIdx.x;
    const int wid  = tid >> 5, lane = tid & 31;
    const int wm   = wid & 1;
    const int wn   = wid >> 1;
    const uint32_t smb = smem_u32(sm);

    const float* bias;
    const __nv_bfloat16 *Sh, *Sl, *Gh, *Gl;
    __nv_bfloat16 *Oh, *Ol;
    float* outf;
    if (dir == 0) {
        Sh = layer ? g_hd_hi : g_xd_hi;  Sl = layer ? g_hd_lo : g_xd_lo;
        Gh = g_aggd_hi[layer]; Gl = g_aggd_lo[layer];
        Oh = g_hd_hi; Ol = g_hd_lo;
        bias = bsh + layer * DIM;
        outf = dout + (size_t)NSRC * DIM;
    } else {
        Sh = layer ? g_hs_hi : g_xs_hi;  Sl = layer ? g_hs_lo : g_xs_lo;
        Gh = g_aggs_hi[layer]; Gl = g_aggs_lo[layer];
        Oh = g_hs_hi; Ol = g_hs_lo;
        bias = brv + layer * DIM;
        outf = dout;
    }
    const __nv_bfloat16* Bhg = g_Bbf[layer][dir][0];
    const __nv_bfloat16* Blg = g_Bbf[layer][dir][1];

    // ---- B: all 4 chunks hi/lo via cp.async, one group ----
#pragma unroll 4
    for (int j = 0; j < 32; j++) {
        int i = j * 256 + tid;
        int pc = i >> 10;
        int cch = pc >> 1, pp = pc & 1;
        int rem = i & 1023;
        int rowi = rem >> 3, piece = rem & 7;
        const __nv_bfloat16* src = (pp ? Blg : Bhg) + rowi * 256 + cch * 64 + piece * 8;
        uint32_t dst = smb + AREG_B + pc * PLANE_B + rowi * 144 + piece * 16;
        CP_ASYNC16(dst, src);
    }
    CP_COMMIT();
    if (tid < DIM) sbias[tid] = bias[tid];

    const int a_row_off = (wm * 64 + (lane & 15)) * SPAD + (lane >> 4) * 8;
    const int b_row_off = (wn * 32 + (lane & 7) + (lane >> 4) * 8) * SPAD + ((lane >> 3) & 1) * 8;

    auto issue_A = [&](int tile, int kc, int st) {
        const __nv_bfloat16* ph = (kc < 2) ? Sh : Gh;
        const __nv_bfloat16* pl = (kc < 2) ? Sl : Gl;
        const int col0 = (kc & 1) * 64;
#pragma unroll
        for (int j = 0; j < 8; j++) {
            int i = j * 256 + tid;
            int pp = i >> 10;
            int rem = i & 1023;
            int rowi = rem >> 3, piece = rem & 7;
            int r = tile * 128 + rowi; if (r > NDST - 1) r = NDST - 1;
            const __nv_bfloat16* src = (pp ? pl : ph) + (size_t)r * DIM + col0 + piece * 8;
            uint32_t dst = smb + (st * 2 + pp) * PLANE_B + rowi * 144 + piece * 16;
            CP_ASYNC16(dst, src);
        }
    };

    int st = 0;
    issue_A(blockIdx.x, 0, 0);
    CP_COMMIT();

    for (int tile = blockIdx.x; tile < TILES; tile += PCTAS) {
        float acc[4][4][4];
#pragma unroll
        for (int i = 0; i < 4; i++)
#pragma unroll
            for (int j = 0; j < 4; j++)
#pragma unroll
                for (int q = 0; q < 4; q++) acc[i][j][q] = 0.f;

#pragma unroll 1
        for (int kc = 0; kc < 4; kc++) {
            int ntile = (kc < 3) ? tile : tile + PCTAS;
            int nkc   = (kc < 3) ? kc + 1 : 0;
            if (ntile < TILES) issue_A(ntile, nkc, st ^ 1);
            CP_COMMIT();
            CP_WAIT1();
            __syncthreads();

            const uint32_t aHi = smb + (st * 2) * PLANE_B + 2 * a_row_off;
            const uint32_t aLo = aHi + PLANE_B;
            const uint32_t bHi = smb + AREG_B + (kc * 2) * PLANE_B + 2 * b_row_off;
            const uint32_t bLo = bHi + PLANE_B;
#pragma unroll
            for (int k16 = 0; k16 < 4; k16++) {
                uint32_t ah[4][4], al[4][4], bh[2][4], bl[2][4];
#pragma unroll
                for (int mt = 0; mt < 4; mt++) {
                    LDSM_X4(ah[mt], aHi + 2 * (mt * 16 * SPAD + k16 * 16));
                    LDSM_X4(al[mt], aLo + 2 * (mt * 16 * SPAD + k16 * 16));
                }
#pragma unroll
                for (int p = 0; p < 2; p++) {
                    LDSM_X4(bh[p], bHi + 2 * (p * 16 * SPAD + k16 * 16));
                    LDSM_X4(bl[p], bLo + 2 * (p * 16 * SPAD + k16 * 16));
                }
#pragma unroll
                for (int mt = 0; mt < 4; mt++)
#pragma unroll
                    for (int nt = 0; nt < 4; nt++) {
                        uint32_t* BH = &bh[nt >> 1][(nt & 1) * 2];
                        uint32_t* BL = &bl[nt >> 1][(nt & 1) * 2];
                        MMA_BF16(acc[mt][nt], ah[mt], BH[0], BH[1]);
                        MMA_BF16(acc[mt][nt], al[mt], BH[0], BH[1]);
                        MMA_BF16(acc[mt][nt], ah[mt], BL[0], BL[1]);
                    }
            }
            __syncthreads();
            st ^= 1;
        }

        // ---- epilogue ----
        const int ebase_r = tile * 128 + wm * 64 + (lane >> 2);
        const int ebase_c = wn * 32 + (lane & 3) * 2;
#pragma unroll
        for (int mt = 0; mt < 4; mt++) {
#pragma unroll
            for (int nt = 0; nt < 4; nt++) {
                const int c = ebase_c + nt * 8;
                const float b0 = sbias[c], b1 = sbias[c + 1];
#pragma unroll
                for (int half = 0; half < 2; half++) {
                    int r = ebase_r + mt * 16 + half * 8;
                    if (r < NDST) {
                        float o0 = fmaxf(acc[mt][nt][half * 2 + 0] + b0, 0.f);
                        float o1 = fmaxf(acc[mt][nt][half * 2 + 1] + b1, 0.f);
                        if (layer == 1) {
                            *(float2*)&outf[(size_t)r * DIM + c] = make_float2(o0, o1);
                        } else {
                            uint32_t h, l;
                            split2(o0, o1, h, l);
                            *(uint32_t*)&Oh[(size_t)r * DIM + c] = h;
                            *(uint32_t*)&Ol[(size_t)r * DIM + c] = l;
                        }
                    }
                }
            }
        }
    }
}

// ---------------------------------------------------------------------------
// Launch: fork/join DAG across two streams (capture-safe pattern)
// ---------------------------------------------------------------------------
struct HxCtx {
    cudaStream_t s2;
    cudaEvent_t evFork, evPrep, evCSR, evD0, evS0, evEnd;
    HxCtx() {
        cudaStreamCreateWithFlags(&s2, cudaStreamNonBlocking);
        cudaEventCreateWithFlags(&evFork, cudaEventDisableTiming);
        cudaEventCreateWithFlags(&evPrep, cudaEventDisableTiming);
        cudaEventCreateWithFlags(&evCSR,  cudaEventDisableTiming);
        cudaEventCreateWithFlags(&evD0,   cudaEventDisableTiming);
        cudaEventCreateWithFlags(&evS0,   cudaEventDisableTiming);
        cudaEventCreateWithFlags(&evEnd,  cudaEventDisableTiming);
    }
};

extern "C" void kernel_launch(void* const* d_in, const int* in_sizes, int n_in,
                              void* d_out, int out_size)
{
    const float* x_src = (const float*)d_in[0];
    const float* x_dst = (const float*)d_in[1];
    const int*   e_src = (const int*)  d_in[2];
    const int*   e_dst = (const int*)  d_in[3];
    const float* Wss   = (const float*)d_in[4];
    const float* Wsn   = (const float*)d_in[5];
    const float* bsh   = (const float*)d_in[6];
    const float* Wrs   = (const float*)d_in[7];
    const float* Wrn   = (const float*)d_in[8];
    const float* brv   = (const float*)d_in[9];
    float* out = (float*)d_out;

    static HxCtx C;   // streams/events created on first call (pre-capture)
    cudaFuncSetAttribute(k_gemm, cudaFuncAttributeMaxDynamicSharedMemorySize, SM_TOTAL);

    // fork
    cudaEventRecord(C.evFork, 0);
    cudaStreamWaitEvent(C.s2, C.evFork, 0);

    // stream B: weight/feature prep (independent of CSR)
    k_prep_B<<<dim3(4, 8), 256, 0, C.s2>>>(Wss, Wsn, Wrs, Wrn);
    k_prep_X<<<(NSRC * DIM / 4 + 255) / 256, 256, 0, C.s2>>>(x_src, x_dst);
    cudaEventRecord(C.evPrep, C.s2);

    // origin: CSR build
    k_zero_cnt<<<(NDST + 255) / 256, 256>>>();
    k_count<<<(NE / 2 + 255) / 256, 256>>>(e_src, e_dst);
    k_blocksum<<<dim3(SCAN_BLK, 2), 256>>>();
    k_write_off<<<dim3(SCAN_BLK, 2), 256>>>();
    k_place<<<(NE + 255) / 256, 256>>>(e_src, e_dst);
    cudaEventRecord(C.evCSR, 0);
    cudaStreamWaitEvent(C.s2, C.evCSR, 0);

    const int GATH_BLKS = (NDST * 32 + 255) / 256;

    // chain B (s2): gth_s0 -> gemm_s0 -> gth_d1 -> gemm_d1
    k_gather<<<GATH_BLKS, 256, 0, C.s2>>>(0, 1, x_src, x_dst);
    k_gemm<<<PCTAS, 256, SM_TOTAL, C.s2>>>(0, 1, bsh, brv, out);   // writes g_hs
    cudaEventRecord(C.evS0, C.s2);
    k_gather<<<GATH_BLKS, 256, 0, C.s2>>>(1, 0, x_src, x_dst);     // reads g_hs -> agg[1]

    // chain A (origin): gth_d0 -> gemm_d0 -> gth_s1 -> gemm_s1
    k_gather<<<GATH_BLKS, 256>>>(0, 0, x_src, x_dst);
    cudaStreamWaitEvent(0, C.evPrep, 0);                           // planes + B images
    k_gemm<<<PCTAS, 256, SM_TOTAL>>>(0, 0, bsh, brv, out);         // writes g_hd
    cudaEventRecord(C.evD0, 0);
    k_gather<<<GATH_BLKS, 256>>>(1, 1, x_src, x_dst);              // reads g_hd -> agg[1]
    cudaStreamWaitEvent(0, C.evS0, 0);                             // self term needs g_hs
    k_gemm<<<PCTAS, 256, SM_TOTAL>>>(1, 1, bsh, brv, out);         // writes dout h_s half

    // chain B tail: gemm_d1 needs g_hd (evD0)
    cudaStreamWaitEvent(C.s2, C.evD0, 0);
    k_gemm<<<PCTAS, 256, SM_TOTAL, C.s2>>>(1, 0, bsh, brv, out);   // writes dout h_d half
    cudaEventRecord(C.evEnd, C.s2);
    cudaStreamWaitEvent(0, C.evEnd, 0);                            // join
}